// round 3
// baseline (speedup 1.0000x reference)
#include <cuda_runtime.h>
#include <cuda_bf16.h>
#include <cstdint>
#include <cstddef>

// Problem constants (from reference: inputs [8192, 64], capacity = ceil(1.25*8192/64)=160)
#define S 8192
#define E 64
#define CAP 160
#define SEC ((size_t)S * E * CAP)   // 83,886,080

// -------- device scratch (allocation-free: __device__ globals) --------
__device__ uint8_t  g_expert[S];   // argmax expert per token
__device__ float    g_prob[S];     // softmax prob at argmax expert
__device__ unsigned g_rbits[S];    // rand[t, expert] bit pattern (uniform [0,1): uint order == float order)

// ============================================================================
// Kernel A: warp per token. Fused argmax (first-index tie-break), softmax
// denominator, prob-at-argmax = 1/sum(exp(x - max)), and rand gather.
// ============================================================================
__global__ void __launch_bounds__(256) router_token_kernel(
    const float* __restrict__ inputs, const float* __restrict__ rand)
{
    int t    = blockIdx.x * 8 + (threadIdx.x >> 5);
    int lane = threadIdx.x & 31;
    if (t >= S) return;

    const float* row = inputs + (size_t)t * E;
    float v0 = row[lane];
    float v1 = row[lane + 32];

    // local max with first-index preference (v0 has the lower index)
    float m;  int mi;
    if (v0 >= v1) { m = v0; mi = lane; } else { m = v1; mi = lane + 32; }

    // butterfly reduce: max value, ties -> smaller index
    #pragma unroll
    for (int o = 16; o > 0; o >>= 1) {
        float om  = __shfl_xor_sync(0xFFFFFFFFu, m, o);
        int   omi = __shfl_xor_sync(0xFFFFFFFFu, mi, o);
        if (om > m || (om == m && omi < mi)) { m = om; mi = omi; }
    }

    // softmax denominator sum(exp(x - max)); prob(argmax) = 1/sum
    float s = expf(v0 - m) + expf(v1 - m);
    #pragma unroll
    for (int o = 16; o > 0; o >>= 1)
        s += __shfl_xor_sync(0xFFFFFFFFu, s, o);

    if (lane == 0) {
        g_expert[t] = (uint8_t)mi;
        g_prob[t]   = 1.0f / s;
        g_rbits[t]  = __float_as_uint(rand[(size_t)t * E + mi]);
    }
}

// ============================================================================
// Block-wide exclusive scan over 256 ints. Returns exclusive prefix; *tot gets
// the block total. Internal __syncthreads makes it safe to call repeatedly.
// ============================================================================
__device__ __forceinline__ int block_excl_scan_256(int v, int* tot, int* warpsums)
{
    int lane = threadIdx.x & 31, wid = threadIdx.x >> 5;
    int inc = v;
    #pragma unroll
    for (int o = 1; o < 32; o <<= 1) {
        int n = __shfl_up_sync(0xFFFFFFFFu, inc, o);
        if (lane >= o) inc += n;
    }
    if (lane == 31) warpsums[wid] = inc;
    __syncthreads();
    if (wid == 0) {
        int sv = (lane < 8) ? warpsums[lane] : 0;
        #pragma unroll
        for (int o = 1; o < 8; o <<= 1) {
            int n = __shfl_up_sync(0xFFFFFFFFu, sv, o);
            if (lane >= o) sv += n;
        }
        if (lane < 8) warpsums[lane] = sv;
    }
    __syncthreads();
    int excl = inc - v + (wid ? warpsums[wid - 1] : 0);
    *tot = warpsums[7];
    __syncthreads();   // protect warpsums for next call
    return excl;
}

// ============================================================================
// Kernel BC: one block (256 thr) per expert.
//  Phase 1: exact 160th-largest rand via 4x 8-bit radix-select on uint bits.
//           Also yields count (= sum of pass-3 histogram) and need_eq
//           (how many bits==T tokens keep, lower token index first — matches
//           jax.lax.top_k tie-breaking).
//  Phase 2: ordered scan over tokens 0..8191 reproducing cumsum(dispatch)-1
//           slot assignment; scatter nonzeros of combine_weights / sec_mask.
// ============================================================================
__global__ void __launch_bounds__(256) router_expert_kernel(
    float* __restrict__ out, int write_mask, long long counts_off)
{
    const int e   = blockIdx.x;
    const int tid = threadIdx.x;

    __shared__ unsigned hist[256];
    __shared__ int s_warpsums[8];
    __shared__ unsigned s_prefix;
    __shared__ int s_k, s_total, s_done;

    if (tid == 0) { s_prefix = 0; s_k = CAP; s_total = 0; s_done = 0; }
    __syncthreads();

    // ---- radix select: find T = CAP-th largest rand bits among assigned ----
    for (int pass = 3; pass >= 0; --pass) {
        if (s_done) break;
        hist[tid] = 0;
        __syncthreads();

        unsigned prefix = s_prefix;
        unsigned himask = (pass == 3) ? 0u : (0xFFFFFFFFu << ((pass + 1) * 8));
        int shift = pass * 8;

        for (int t = tid; t < S; t += 256) {
            if (g_expert[t] == (uint8_t)e) {
                unsigned b = g_rbits[t];
                if ((b & himask) == (prefix & himask))
                    atomicAdd(&hist[(b >> shift) & 255u], 1u);
            }
        }
        __syncthreads();

        if (tid == 0) {
            if (pass == 3) {
                int total = 0;
                for (int i = 0; i < 256; ++i) total += (int)hist[i];
                s_total = total;
                if (total <= CAP) {       // all assigned tokens kept
                    s_prefix = 0u;
                    s_k = CAP;
                    s_done = 1;
                }
            }
            if (!s_done) {
                int k = s_k, acc = 0, bin = 0;
                for (int i = 255; i >= 0; --i) {
                    int h = (int)hist[i];
                    if (acc + h >= k) { bin = i; break; }
                    acc += h;
                }
                s_k = k - acc;            // remaining rank within chosen bin
                s_prefix = s_prefix | ((unsigned)bin << shift);
            }
        }
        __syncthreads();
    }

    const unsigned T       = s_prefix;
    const int      need_eq = s_k;       // #(bits==T) tokens to keep (lowest index first)
    const int      total   = s_total;

    // ---- ordered scan: slot assignment + scatter ----
    int runEq = 0, runKept = 0;
    const size_t mask_base = SEC;

    for (int chunk = 0; chunk < S / 256; ++chunk) {
        int t = chunk * 256 + tid;
        bool assigned = (g_expert[t] == (uint8_t)e);
        unsigned b = assigned ? g_rbits[t] : 0u;
        int eqf = (assigned && b == T) ? 1 : 0;
        int gtf = (assigned && b >  T) ? 1 : 0;

        int eqTot;
        int eq_excl = block_excl_scan_256(eqf, &eqTot, s_warpsums);

        int kept = (gtf || (eqf && (runEq + eq_excl) < need_eq)) ? 1 : 0;

        int keptTot;
        int k_excl = block_excl_scan_256(kept, &keptTot, s_warpsums);

        if (kept) {
            int loc = runKept + k_excl;   // cumsum(dispatch)-1 slot
            size_t off = (size_t)t * (E * CAP) + (size_t)e * CAP + loc;
            out[off] = g_prob[t];
            if (write_mask) out[mask_base + off] = 1.0f;
        }
        runEq   += eqTot;
        runKept += keptTot;
    }

    if (tid == 0 && counts_off >= 0)
        out[(size_t)counts_off + e] = (float)total;
}

// ============================================================================
// Launch
// ============================================================================
extern "C" void kernel_launch(void* const* d_in, const int* in_sizes, int n_in,
                              void* d_out, int out_size)
{
    const float* inputs = (const float*)d_in[0];  // [8192, 64] f32
    const float* rand   = (const float*)d_in[1];  // [8192, 64] f32
    float* out = (float*)d_out;

    size_t osz = (size_t)out_size;

    // Zero field: output is >99.99% zeros. Memset is the bandwidth-optimal path.
    cudaMemsetAsync(d_out, 0, osz * sizeof(float), 0);

    // Per-token: argmax + softmax-at-argmax + rand gather
    router_token_kernel<<<S / 8, 256>>>(inputs, rand);

    // Layout probing (out = combine ‖ [sec_mask] ‖ [exp_counts])
    int write_mask = (osz >= 2 * SEC) ? 1 : 0;
    long long counts_off = -1;
    if (osz > SEC && (osz % SEC) == (size_t)E) counts_off = (long long)(osz - E);

    // Per-expert: capacity selection + slot scan + scatter
    router_expert_kernel<<<E, 256>>>(out, write_mask, counts_off);
}

// round 4
// speedup vs baseline: 1.2078x; 1.2078x over previous
#include <cuda_runtime.h>
#include <cuda_bf16.h>
#include <cstdint>
#include <cstddef>

// Problem constants: inputs [8192, 64], capacity = ceil(1.25*8192/64) = 160
#define S   8192
#define E   64
#define CAP 160
#define ROW (E * CAP)               // 10240 floats per token row
#define SEC ((size_t)S * ROW)       // 83,886,080 elements per [s,e,c] section

// -------- device scratch (allocation-free: __device__ globals) --------
__device__ uint8_t  g_expert[S];    // argmax expert per token
__device__ float    g_prob[S];      // softmax prob at argmax expert
__device__ unsigned g_rbits[S];     // rand[t, argmax] bits (uniform [0,1): uint order == float order)
__device__ int      g_loc[S];       // capacity slot per token, -1 if dropped

// ============================================================================
// Kernel A: warp per token. Fused argmax (lower-index tie-break), softmax
// denominator, prob-at-argmax = 1/sum(exp(x - max)), and rand gather.
// ============================================================================
__global__ void __launch_bounds__(256) router_token_kernel(
    const float* __restrict__ inputs, const float* __restrict__ rand)
{
    int t    = blockIdx.x * 8 + (threadIdx.x >> 5);
    int lane = threadIdx.x & 31;
    if (t >= S) return;

    const float* row = inputs + (size_t)t * E;
    float v0 = row[lane];
    float v1 = row[lane + 32];

    float m;  int mi;
    if (v0 >= v1) { m = v0; mi = lane; } else { m = v1; mi = lane + 32; }

    #pragma unroll
    for (int o = 16; o > 0; o >>= 1) {
        float om  = __shfl_xor_sync(0xFFFFFFFFu, m, o);
        int   omi = __shfl_xor_sync(0xFFFFFFFFu, mi, o);
        if (om > m || (om == m && omi < mi)) { m = om; mi = omi; }
    }

    float s = expf(v0 - m) + expf(v1 - m);
    #pragma unroll
    for (int o = 16; o > 0; o >>= 1)
        s += __shfl_xor_sync(0xFFFFFFFFu, s, o);

    if (lane == 0) {
        g_expert[t] = (uint8_t)mi;
        g_prob[t]   = 1.0f / s;
        g_rbits[t]  = __float_as_uint(rand[(size_t)t * E + mi]);
    }
}

// ============================================================================
// Block-wide inclusive scan over 1024 ints. All threads must call.
// *tot receives the block total. Safe to call repeatedly (internal syncs).
// ============================================================================
__device__ __forceinline__ int block_incl_scan_1024(int v, int* tot, int* warpsums)
{
    int lane = threadIdx.x & 31, w = threadIdx.x >> 5;
    int inc = v;
    #pragma unroll
    for (int o = 1; o < 32; o <<= 1) {
        int n = __shfl_up_sync(0xFFFFFFFFu, inc, o);
        if (lane >= o) inc += n;
    }
    if (lane == 31) warpsums[w] = inc;
    __syncthreads();
    if (w == 0) {
        int sv = warpsums[lane];
        #pragma unroll
        for (int o = 1; o < 32; o <<= 1) {
            int n = __shfl_up_sync(0xFFFFFFFFu, sv, o);
            if (lane >= o) sv += n;
        }
        warpsums[lane] = sv;
    }
    __syncthreads();
    int res = inc + (w ? warpsums[w - 1] : 0);
    *tot = warpsums[31];
    __syncthreads();   // protect warpsums for next call
    return res;
}

// ============================================================================
// Kernel B: one block (1024 thr) per expert.
//  Phase 1: exact CAP-th largest rand bits via radix-select (common case: one
//           pass, since count <= CAP for ~99.8% of experts). Bin selection via
//           parallel suffix scan (no serial tid==0 loops).
//  Phase 2: ONE packed (eq|gt) block scan per 1024-token chunk reproduces the
//           cumsum slot assignment: loc = gt_excl + min(eq_excl, need_eq).
//  Emits g_loc[] (slot or -1) and exp_counts.
// ============================================================================
__global__ void __launch_bounds__(1024) router_select_kernel(
    float* __restrict__ out, long long counts_off)
{
    const int e   = blockIdx.x;
    const int tid = threadIdx.x;

    __shared__ unsigned hist[256];
    __shared__ int s_warpsums[32];
    __shared__ unsigned s_prefix;
    __shared__ int s_k, s_total, s_done;

    if (tid == 0) { s_prefix = 0; s_k = CAP; s_total = 0; s_done = 0; }

    // ---- radix select over rand bits ----
    for (int pass = 3; pass >= 0; --pass) {
        __syncthreads();
        if (s_done) break;
        if (tid < 256) hist[tid] = 0;
        __syncthreads();

        unsigned prefix = s_prefix;
        unsigned himask = (pass == 3) ? 0u : (0xFFFFFFFFu << ((pass + 1) * 8));
        int shift = pass * 8;

        #pragma unroll
        for (int c = 0; c < S / 1024; ++c) {
            int t = c * 1024 + tid;
            if (g_expert[t] == (uint8_t)e) {
                unsigned b = g_rbits[t];
                if ((b & himask) == (prefix & himask))
                    atomicAdd(&hist[(b >> shift) & 255u], 1u);
            }
        }
        __syncthreads();

        // suffix-sum scan: thread tid handles bin i = 255 - tid
        int hv = (tid < 256) ? (int)hist[255 - tid] : 0;
        int tot;
        int suf = block_incl_scan_1024(hv, &tot, s_warpsums);   // = sum over bins >= i

        int k = s_k;   // stable: no writer since last sync
        __syncthreads();

        if (tid < 256) {
            int i = 255 - tid;
            int above = suf - hv;                  // count strictly greater than bin i
            if (pass == 3 && tid == 255) {
                s_total = suf;                     // total assigned to this expert
                if (suf <= CAP) s_done = 1;        // keep everything
            }
            if (suf >= k && above < k) {           // unique selected bin
                s_k = k - above;
                s_prefix = prefix | ((unsigned)i << shift);
            }
        }
    }
    __syncthreads();

    const int keep_all   = (s_total <= CAP);
    const unsigned T     = s_prefix;
    const int need_eq    = keep_all ? 0 : s_k;   // #(bits==T) kept, lowest index first
    const int total      = s_total;

    // ---- ordered slot assignment ----
    int runEq = 0, runGt = 0;
    #pragma unroll
    for (int c = 0; c < S / 1024; ++c) {
        int t = c * 1024 + tid;
        bool assigned = (g_expert[t] == (uint8_t)e);
        unsigned b = assigned ? g_rbits[t] : 0u;
        int gtf, eqf;
        if (keep_all) { gtf = assigned ? 1 : 0; eqf = 0; }
        else {
            gtf = (assigned && b >  T) ? 1 : 0;
            eqf = (assigned && b == T) ? 1 : 0;
        }
        int packed = eqf | (gtf << 16);

        int tot;
        int incl = block_incl_scan_1024(packed, &tot, s_warpsums);
        int excl = incl - packed;
        int eq_excl = runEq + (excl & 0xFFFF);
        int gt_excl = runGt + (excl >> 16);

        if (assigned) {
            int kept = gtf || (eqf && eq_excl < need_eq);
            int loc  = gt_excl + min(eq_excl, need_eq);
            g_loc[t] = kept ? loc : -1;
        }
        runEq += tot & 0xFFFF;
        runGt += tot >> 16;
    }

    if (tid == 0 && counts_off >= 0)
        out[(size_t)counts_off + e] = (float)total;
}

// ============================================================================
// Kernel C: fused zero-fill + scatter. Block per token; each thread stores
// 10 (+10 mask) float4 with immediate offsets, then the owning thread
// re-stores the one nonzero float4 (same-thread program order).
// ============================================================================
__global__ void __launch_bounds__(256) router_fill_kernel(
    float* __restrict__ out, int write_mask)
{
    const int t   = blockIdx.x;
    const int tid = threadIdx.x;
    const float4 z = make_float4(0.f, 0.f, 0.f, 0.f);

    float4* base  = (float4*)out + (size_t)t * (ROW / 4);
    float4* mbase = base + (SEC / 4);

    #pragma unroll
    for (int i = 0; i < ROW / 4 / 256; ++i)       // 10 iterations
        base[tid + 256 * i] = z;
    if (write_mask) {
        #pragma unroll
        for (int i = 0; i < ROW / 4 / 256; ++i)
            mbase[tid + 256 * i] = z;
    }

    int loc = g_loc[t];
    if (loc >= 0) {
        int nz  = (int)g_expert[t] * CAP + loc;
        int nz4 = nz >> 2;
        if (tid == (nz4 & 255)) {
            int r = nz & 3;
            float4 v = z; ((float*)&v)[r] = g_prob[t];
            base[nz4] = v;
            if (write_mask) {
                float4 m = z; ((float*)&m)[r] = 1.0f;
                mbase[nz4] = m;
            }
        }
    }
}

// ============================================================================
// Launch:  tail-zero -> token -> select (writes counts) -> fused fill
// ============================================================================
extern "C" void kernel_launch(void* const* d_in, const int* in_sizes, int n_in,
                              void* d_out, int out_size)
{
    const float* inputs = (const float*)d_in[0];  // [8192, 64] f32
    const float* rand   = (const float*)d_in[1];  // [8192, 64] f32
    float* out = (float*)d_out;
    size_t osz = (size_t)out_size;

    // Layout: out = combine_weights [s,e,c] ‖ sec_mask [s,e,c] ‖ exp_counts [e]
    int write_mask = (osz >= 2 * SEC) ? 1 : 0;
    long long counts_off = -1;
    if (osz > SEC && (osz % SEC) == (size_t)E) counts_off = (long long)(osz - E);

    // Zero any bytes past the regions the fill kernel covers (normally just
    // the 64-float counts slice, which select overwrites afterwards).
    size_t covered = write_mask ? 2 * SEC : SEC;
    if (osz > covered)
        cudaMemsetAsync((char*)d_out + covered * sizeof(float), 0,
                        (osz - covered) * sizeof(float), 0);

    router_token_kernel<<<S / 8, 256>>>(inputs, rand);
    router_select_kernel<<<E, 1024>>>(out, counts_off);
    router_fill_kernel<<<S, 256>>>(out, write_mask);
}

// round 5
// speedup vs baseline: 1.2164x; 1.0072x over previous
#include <cuda_runtime.h>
#include <cuda_bf16.h>
#include <cstdint>
#include <cstddef>

// Problem constants: inputs [8192, 64], capacity = ceil(1.25*8192/64) = 160
#define S   8192
#define E   64
#define CAP 160
#define ROW (E * CAP)               // 10240 floats per token row
#define SEC ((size_t)S * ROW)       // 83,886,080 elements per [s,e,c] section
#define TOK_PER_BLK 4
#define FILL_BLKS (S / TOK_PER_BLK) // 2048

// -------- device scratch (allocation-free: __device__ globals) --------
__device__ uint8_t  g_expert[S];    // argmax expert per token
__device__ float    g_prob[S];      // softmax prob at argmax expert
__device__ unsigned g_rbits[S];     // rand[t, argmax] bits (uniform [0,1): uint order == float order)
__device__ int      g_loc[S];       // capacity slot per token, -1 if dropped

// ============================================================================
// K1: warp per token. float2 loads, fused argmax (lower-index tie-break),
// softmax denom, prob-at-argmax = 1/sum(exp(x-max)), rand gather.
// Triggers PDL completion at entry so K2 can co-schedule.
// ============================================================================
__global__ void __launch_bounds__(256) router_token_kernel(
    const float* __restrict__ inputs, const float* __restrict__ rand)
{
#if __CUDA_ARCH__ >= 900
    cudaTriggerProgrammaticLaunchCompletion();
#endif
    int t    = blockIdx.x * 8 + (threadIdx.x >> 5);
    int lane = threadIdx.x & 31;

    float2 v = ((const float2*)(inputs + (size_t)t * E))[lane];

    float m;  int mi;
    if (v.x >= v.y) { m = v.x; mi = 2 * lane; } else { m = v.y; mi = 2 * lane + 1; }

    #pragma unroll
    for (int o = 16; o > 0; o >>= 1) {
        float om  = __shfl_xor_sync(0xFFFFFFFFu, m, o);
        int   omi = __shfl_xor_sync(0xFFFFFFFFu, mi, o);
        if (om > m || (om == m && omi < mi)) { m = om; mi = omi; }
    }

    float s = expf(v.x - m) + expf(v.y - m);
    #pragma unroll
    for (int o = 16; o > 0; o >>= 1)
        s += __shfl_xor_sync(0xFFFFFFFFu, s, o);

    if (lane == 0) {
        g_expert[t] = (uint8_t)mi;
        g_prob[t]   = 1.0f / s;
        g_rbits[t]  = __float_as_uint(rand[(size_t)t * E + mi]);
    }
}

// ============================================================================
// Block-wide inclusive scan over 1024 ints. *tot = block total.
// Safe to call repeatedly (internal syncs).
// ============================================================================
__device__ __forceinline__ int block_incl_scan_1024(int v, int* tot, int* warpsums)
{
    int lane = threadIdx.x & 31, w = threadIdx.x >> 5;
    int inc = v;
    #pragma unroll
    for (int o = 1; o < 32; o <<= 1) {
        int n = __shfl_up_sync(0xFFFFFFFFu, inc, o);
        if (lane >= o) inc += n;
    }
    if (lane == 31) warpsums[w] = inc;
    __syncthreads();
    if (w == 0) {
        int sv = warpsums[lane];
        #pragma unroll
        for (int o = 1; o < 32; o <<= 1) {
            int n = __shfl_up_sync(0xFFFFFFFFu, sv, o);
            if (lane >= o) sv += n;
        }
        warpsums[lane] = sv;
    }
    __syncthreads();
    int res = inc + (w ? warpsums[w - 1] : 0);
    *tot = warpsums[31];
    __syncthreads();
    return res;
}

// ============================================================================
// K2: one block (1024 thr) per expert. PDL: trigger (release K3), then grid-
// dependency sync (wait K1 data), then exact radix-select + ordered slot scan.
// Emits g_loc[] (slot or -1) and exp_counts.
// ============================================================================
__global__ void __launch_bounds__(1024) router_select_kernel(
    float* __restrict__ out, long long counts_off)
{
#if __CUDA_ARCH__ >= 900
    cudaTriggerProgrammaticLaunchCompletion();
    cudaGridDependencySynchronize();
#endif
    const int e   = blockIdx.x;
    const int tid = threadIdx.x;

    __shared__ unsigned hist[256];
    __shared__ int s_warpsums[32];
    __shared__ unsigned s_prefix;
    __shared__ int s_k, s_total, s_done;

    if (tid == 0) { s_prefix = 0; s_k = CAP; s_total = 0; s_done = 0; }

    // ---- radix select over rand bits (common case: 1 pass, count <= CAP) ----
    for (int pass = 3; pass >= 0; --pass) {
        __syncthreads();
        if (s_done) break;
        if (tid < 256) hist[tid] = 0;
        __syncthreads();

        unsigned prefix = s_prefix;
        unsigned himask = (pass == 3) ? 0u : (0xFFFFFFFFu << ((pass + 1) * 8));
        int shift = pass * 8;

        #pragma unroll
        for (int c = 0; c < S / 1024; ++c) {
            int t = c * 1024 + tid;
            if (g_expert[t] == (uint8_t)e) {
                unsigned b = g_rbits[t];
                if ((b & himask) == (prefix & himask))
                    atomicAdd(&hist[(b >> shift) & 255u], 1u);
            }
        }
        __syncthreads();

        // suffix-sum: thread tid handles bin i = 255 - tid
        int hv = (tid < 256) ? (int)hist[255 - tid] : 0;
        int tot;
        int suf = block_incl_scan_1024(hv, &tot, s_warpsums);

        int k = s_k;   // stable: no writer since last sync
        __syncthreads();

        if (tid < 256) {
            int i = 255 - tid;
            int above = suf - hv;                  // strictly greater than bin i
            if (pass == 3 && tid == 255) {
                s_total = suf;
                if (suf <= CAP) s_done = 1;        // keep everything
            }
            if (suf >= k && above < k) {           // unique selected bin
                s_k = k - above;
                s_prefix = prefix | ((unsigned)i << shift);
            }
        }
    }
    __syncthreads();

    const int keep_all = (s_total <= CAP);
    const unsigned T   = s_prefix;
    const int need_eq  = keep_all ? 0 : s_k;   // #(bits==T) kept, lowest index first
    const int total    = s_total;

    // ---- ordered slot assignment: loc = gt_excl + min(eq_excl, need_eq) ----
    int runEq = 0, runGt = 0;
    #pragma unroll
    for (int c = 0; c < S / 1024; ++c) {
        int t = c * 1024 + tid;
        bool assigned = (g_expert[t] == (uint8_t)e);
        unsigned b = assigned ? g_rbits[t] : 0u;
        int gtf, eqf;
        if (keep_all) { gtf = assigned ? 1 : 0; eqf = 0; }
        else {
            gtf = (assigned && b >  T) ? 1 : 0;
            eqf = (assigned && b == T) ? 1 : 0;
        }
        int packed = eqf | (gtf << 16);

        int tot;
        int incl = block_incl_scan_1024(packed, &tot, s_warpsums);
        int excl = incl - packed;
        int eq_excl = runEq + (excl & 0xFFFF);
        int gt_excl = runGt + (excl >> 16);

        if (assigned) {
            int kept = gtf || (eqf && eq_excl < need_eq);
            int loc  = gt_excl + min(eq_excl, need_eq);
            g_loc[t] = kept ? loc : -1;
        }
        runEq += tot & 0xFFFF;
        runGt += tot >> 16;
    }

    if (tid == 0 && counts_off >= 0)
        out[(size_t)counts_off + e] = (float)total;
}

// ============================================================================
// K3: fused zero-fill + fix-up, PDL-overlapped. 4 token-rows per block.
// Streams zeros immediately (no dependency), then grid-dependency sync
// (K2's g_loc visible), __syncthreads (in-block ordering), fix up own tokens.
// ============================================================================
__global__ void __launch_bounds__(256) router_fill_kernel(
    float* __restrict__ out, int write_mask)
{
    const int b   = blockIdx.x;
    const int tid = threadIdx.x;
    const float4 z = make_float4(0.f, 0.f, 0.f, 0.f);

    float4* base  = (float4*)out + (size_t)b * (TOK_PER_BLK * ROW / 4);
    float4* mbase = base + (SEC / 4);

    #pragma unroll
    for (int i = 0; i < TOK_PER_BLK * ROW / 4 / 256; ++i)   // 40 iterations
        base[tid + 256 * i] = z;
    if (write_mask) {
        #pragma unroll
        for (int i = 0; i < TOK_PER_BLK * ROW / 4 / 256; ++i)
            mbase[tid + 256 * i] = z;
    }

#if __CUDA_ARCH__ >= 900
    cudaGridDependencySynchronize();   // K2 done -> g_loc/g_expert/g_prob valid
#endif
    __syncthreads();                   // order fix-up after this block's zeros

    if (tid < TOK_PER_BLK) {
        int t = b * TOK_PER_BLK + tid;
        int loc = g_loc[t];
        if (loc >= 0) {
            size_t off = (size_t)t * ROW + (size_t)g_expert[t] * CAP + loc;
            out[off] = g_prob[t];
            if (write_mask) out[SEC + off] = 1.0f;
        }
    }
}

// ============================================================================
// Launch:  K1 (normal) -> K2 (PDL) -> K3 (PDL).  K3's zero-fill overlaps
// K1+K2; its fix-up waits on K2 via cudaGridDependencySynchronize.
// ============================================================================
extern "C" void kernel_launch(void* const* d_in, const int* in_sizes, int n_in,
                              void* d_out, int out_size)
{
    const float* inputs = (const float*)d_in[0];  // [8192, 64] f32
    const float* rand   = (const float*)d_in[1];  // [8192, 64] f32
    float* out = (float*)d_out;
    size_t osz = (size_t)out_size;

    // Layout: out = combine_weights [s,e,c] | sec_mask [s,e,c] | exp_counts [e]
    int write_mask = (osz >= 2 * SEC) ? 1 : 0;
    long long counts_off = -1;
    if (osz > SEC && (osz % SEC) == (size_t)E) counts_off = (long long)(osz - E);

    // Fallback zero for any bytes not covered by fill or counts writes
    // (standard layout 2*SEC + 64: nothing to do).
    size_t covered = write_mask ? 2 * SEC : SEC;
    size_t counts_bytes = (counts_off >= 0) ? (size_t)E : 0;
    if (osz > covered + counts_bytes)
        cudaMemsetAsync((char*)d_out + covered * sizeof(float), 0,
                        (osz - covered - counts_bytes) * sizeof(float), 0);

    // K1: normal launch (triggers PDL completion at entry)
    router_token_kernel<<<S / 8, 256>>>(inputs, rand);

    cudaLaunchAttribute pdl[1];
    pdl[0].id = cudaLaunchAttributeProgrammaticStreamSerialization;
    pdl[0].val.programmaticStreamSerializationAllowed = 1;

    // K2: select, PDL-overlapped with K1
    {
        cudaLaunchConfig_t cfg = {};
        cfg.gridDim  = dim3(E);
        cfg.blockDim = dim3(1024);
        cfg.stream   = 0;
        cfg.attrs    = pdl;
        cfg.numAttrs = 1;
        cudaLaunchKernelEx(&cfg, router_select_kernel, out, counts_off);
    }

    // K3: fill, PDL-overlapped with K2 (and transitively K1)
    {
        cudaLaunchConfig_t cfg = {};
        cfg.gridDim  = dim3(FILL_BLKS);
        cfg.blockDim = dim3(256);
        cfg.stream   = 0;
        cfg.attrs    = pdl;
        cfg.numAttrs = 1;
        cudaLaunchKernelEx(&cfg, router_fill_kernel, out, write_mask);
    }
}